// round 1
// baseline (speedup 1.0000x reference)
#include <cuda_runtime.h>
#include <math.h>

#define GD     17
#define NS     4096
#define DD     768
#define NHH    30
#define CHH    31
#define NCELL  4913      /* 17^3 */
#define NCHUNK 64
#define CHUNK  64
#define K4_CG  296
#define K4_GRID (K4_CG*2)
#define HH     15        /* h per group */
#define MAXCAND 1536

/* ---------------- scratch (static device globals: allocation-free) ------- */
__device__ __align__(16) float g_w[NS][12];
__device__             int    g_cells[NS][3];
__device__             float  g_dist[NS];
__device__             int    g_bin[NS];
__device__             int    g_binCount[NCELL];
__device__             int    g_binStart[NCELL + 1];
__device__             int    g_binCursor[NCELL];
__device__             int    g_binSamples[NS];
__device__ __align__(16) float g_sd[NS * DD];
__device__ __align__(16) float g_wgt[NS * DD];
__device__ __align__(16) float g_S[NCHUNK * DD];
__device__ __align__(16) float g_A[NCELL * DD];
__device__ __align__(16) float g_part[K4_GRID * HH * DD];

/* ---------------- K-zero: clear bin counts ------------------------------- */
__global__ void k_zero() {
    int i = blockIdx.x * blockDim.x + threadIdx.x;
    if (i < NCELL) g_binCount[i] = 0;
}

/* ---------------- K0: per-sample prep (weights, cells, dist, bin) -------- */
__global__ void k_prep(const float* __restrict__ samples,
                       const float* __restrict__ lastp) {
    int n = blockIdx.x * blockDim.x + threadIdx.x;
    if (n >= NS) return;

    float s[3] = { samples[3*n], samples[3*n+1], samples[3*n+2] };
    float nx[3];
    if (n < NS - 1) { nx[0]=samples[3*n+3]; nx[1]=samples[3*n+4]; nx[2]=samples[3*n+5]; }
    else            { nx[0]=lastp[0];       nx[1]=lastp[1];       nx[2]=lastp[2]; }
    float e0=s[0]-nx[0], e1=s[1]-nx[1], e2=s[2]-nx[2];
    g_dist[n] = sqrtf(e0*e0 + e1*e1 + e2*e2);

    int fi[3];
    #pragma unroll
    for (int a = 0; a < 3; a++) {
        float p  = s[a] + 8.0f;
        float f  = floorf(p);
        int  fii = (int)f;
        float dd = p - f;
        int  q   = (a == 0) ? (fii + 1) : (int)ceilf(p);   /* x uses f+1; y,z use ceil */
        int c0 = fii;
        int c1 = min(q, GD - 1);
        int c2 = max(fii - 1, 0);
        int c3 = min(q + 1, GD - 1);
        float mlo = (fii > 0)      ? 1.0f : 0.0f;
        float mhi = (fii + 2 < GD) ? 1.0f : 0.0f;
        float inv = 1.0f / (2.0f + mlo + mhi);
        g_w[n][a*4+0] = (2.0f - dd) * inv;
        g_w[n][a*4+1] = (1.0f + dd) * inv;
        g_w[n][a*4+2] = (1.0f - dd) * mlo * inv;
        g_w[n][a*4+3] = dd * mhi * inv;
        g_cells[n][a] = c0 | (c1 << 8) | (c2 << 16) | (c3 << 24);
        fi[a] = fii;
    }
    int bin = (fi[0]*GD + fi[1])*GD + fi[2];
    g_bin[n] = bin;
    atomicAdd(&g_binCount[bin], 1);
}

/* ---------------- K-scan: exclusive prefix over bin counts --------------- */
__global__ void k_scan() {
    __shared__ int sm[1024];
    __shared__ int carry;
    int t = threadIdx.x;
    if (t == 0) carry = 0;
    __syncthreads();
    for (int base = 0; base < NCELL; base += 1024) {
        int idx = base + t;
        int v = (idx < NCELL) ? g_binCount[idx] : 0;
        sm[t] = v;
        __syncthreads();
        for (int off = 1; off < 1024; off <<= 1) {
            int x = (t >= off) ? sm[t - off] : 0;
            __syncthreads();
            sm[t] += x;
            __syncthreads();
        }
        if (idx < NCELL) {
            int excl = carry + sm[t] - v;
            g_binStart[idx]  = excl;
            g_binCursor[idx] = excl;
        }
        __syncthreads();
        if (t == 0) carry += sm[1023];
        __syncthreads();
    }
    if (t == 0) g_binStart[NCELL] = carry;
}

/* ---------------- K0c: scatter sample ids into bins ---------------------- */
__global__ void k_scatter() {
    int n = blockIdx.x * blockDim.x + threadIdx.x;
    if (n >= NS) return;
    int pos = atomicAdd(&g_binCursor[g_bin[n]], 1);
    g_binSamples[pos] = n;
}

/* ---------------- K0d: sort each bin (determinism) ----------------------- */
__global__ void k_sortbins() {
    int b = blockIdx.x * blockDim.x + threadIdx.x;
    if (b >= NCELL) return;
    int s0 = g_binStart[b], s1 = g_binStart[b + 1];
    for (int i = s0 + 1; i < s1; i++) {
        int v = g_binSamples[i];
        int j = i - 1;
        while (j >= s0 && g_binSamples[j] > v) { g_binSamples[j+1] = g_binSamples[j]; j--; }
        g_binSamples[j + 1] = v;
    }
}

/* ---------------- K1: density channel interp -> sd ----------------------- */
__global__ void __launch_bounds__(192) k_density(const float* __restrict__ E) {
    __shared__ float scoef[64];
    __shared__ int   soff[64];
    __shared__ float sw[12];
    __shared__ int   sc[3];
    int n = blockIdx.x;
    int t = threadIdx.x;
    if (t < 12) sw[t] = g_w[n][t];
    if (t < 3)  sc[t] = g_cells[n][t];
    __syncthreads();
    if (t < 64) {
        int i = t >> 4, j = (t >> 2) & 3, k = t & 3;
        int cx = (sc[0] >> (8*i)) & 255;
        int cy = (sc[1] >> (8*j)) & 255;
        int cz = (sc[2] >> (8*k)) & 255;
        scoef[t] = sw[i] * sw[4 + j] * sw[8 + k];
        soff[t]  = ((cx*GD + cy)*GD + cz) * (CHH*DD) + NHH*DD;
    }
    __syncthreads();
    int d4 = t * 4;
    float ax = 0.f, ay = 0.f, az = 0.f, aw = 0.f;
    #pragma unroll 4
    for (int m = 0; m < 64; m++) {
        float c = scoef[m];
        if (c != 0.0f) {
            float4 e = *reinterpret_cast<const float4*>(E + soff[m] + d4);
            ax += c * e.x; ay += c * e.y; az += c * e.z; aw += c * e.w;
        }
    }
    float dist = g_dist[n];
    float4 o;
    o.x = fmaxf(ax, 0.f) * dist;
    o.y = fmaxf(ay, 0.f) * dist;
    o.z = fmaxf(az, 0.f) * dist;
    o.w = fmaxf(aw, 0.f) * dist;
    *reinterpret_cast<float4*>(g_sd + n*DD + d4) = o;
}

/* ---------------- K2a: chunk partial sums of sd --------------------------- */
__global__ void k_chunksum() {
    int idx = blockIdx.x * blockDim.x + threadIdx.x;   /* NCHUNK*DD threads */
    int chunk = idx / DD;
    int d = idx - chunk * DD;
    int base = chunk * CHUNK * DD + d;
    float s = 0.f;
    #pragma unroll 8
    for (int i = 0; i < CHUNK; i++) s += g_sd[base + i*DD];
    g_S[chunk*DD + d] = s;
}

/* ---------------- K2b: exclusive scan + weights --------------------------- */
__global__ void k_wgt() {
    int idx = blockIdx.x * blockDim.x + threadIdx.x;
    int chunk = idx / DD;
    int d = idx - chunk * DD;
    float excl = 0.f;
    for (int j = 0; j < chunk; j++) excl += g_S[j*DD + d];
    int base = chunk * CHUNK * DD + d;
    for (int i = 0; i < CHUNK; i++) {
        float sd = g_sd[base + i*DD];
        float T = __expf(-excl);
        float alpha = 1.0f - __expf(-sd);
        g_wgt[base + i*DD] = T * alpha;
        excl += sd;
    }
}

/* ---------------- K3: A[c,d] gather (cell-centric, no atomics) ------------ */
__global__ void __launch_bounds__(192) k_A() {
    __shared__ int   slist[MAXCAND];
    __shared__ float scoef[MAXCAND];
    __shared__ int   scnt[64];
    __shared__ int   soff2[64];
    __shared__ int   sstart[64];
    __shared__ int   s_tot;
    int c = blockIdx.x;
    int iz = c % GD; int r = c / GD; int iy = r % GD; int ix = r / GD;
    int x0 = max(ix-2,0), x1 = min(ix+1,GD-1);
    int y0 = max(iy-2,0), y1 = min(iy+1,GD-1);
    int z0 = max(iz-2,0), z1 = min(iz+1,GD-1);
    int nxb = x1-x0+1, nyb = y1-y0+1, nzb = z1-z0+1;
    int nb = nxb * nyb * nzb;
    int t = threadIdx.x;

    if (t < nb) {
        int bi = t / (nyb*nzb); int rr = t - bi*(nyb*nzb);
        int bj = rr / nzb;      int bk = rr - bj*nzb;
        int b = ((x0+bi)*GD + (y0+bj))*GD + (z0+bk);
        sstart[t] = g_binStart[b];
        scnt[t]   = g_binStart[b+1] - g_binStart[b];
    }
    __syncthreads();
    if (t == 0) {
        int acc = 0;
        for (int i = 0; i < nb; i++) { soff2[i] = acc; acc += scnt[i]; }
        s_tot = (acc < MAXCAND) ? acc : MAXCAND;
    }
    __syncthreads();
    int tot = s_tot;
    if (t < nb) {
        int off = soff2[t], st = sstart[t], cn = scnt[t];
        for (int k = 0; k < cn; k++)
            if (off + k < MAXCAND) slist[off + k] = g_binSamples[st + k];
    }
    __syncthreads();
    /* coefficients: one candidate per thread */
    for (int i = t; i < tot; i += 192) {
        int n = slist[i];
        int cpx = g_cells[n][0], cpy = g_cells[n][1], cpz = g_cells[n][2];
        float wx = 0.f, wy = 0.f, wz = 0.f;
        #pragma unroll
        for (int u = 0; u < 4; u++) {
            if (((cpx >> (8*u)) & 255) == ix) wx += g_w[n][u];
            if (((cpy >> (8*u)) & 255) == iy) wy += g_w[n][4 + u];
            if (((cpz >> (8*u)) & 255) == iz) wz += g_w[n][8 + u];
        }
        scoef[i] = wx * wy * wz;
        slist[i] = n * DD;
    }
    __syncthreads();
    int d4 = t * 4;
    float ax = 0.f, ay = 0.f, az = 0.f, aw = 0.f;
    for (int i = 0; i < tot; i++) {
        float cf = scoef[i];
        if (cf != 0.0f) {
            float4 wv = *reinterpret_cast<const float4*>(g_wgt + slist[i] + d4);
            ax += cf * wv.x; ay += cf * wv.y; az += cf * wv.z; aw += cf * wv.w;
        }
    }
    float4 o; o.x = ax; o.y = ay; o.z = az; o.w = aw;
    *reinterpret_cast<float4*>(g_A + c*DD + d4) = o;
}

/* ---------------- K4: out partials = sum_c A[c,d]*E[c,h,d] ---------------- */
__global__ void __launch_bounds__(192, 2) k_out(const float* __restrict__ E) {
    int cg = blockIdx.x >> 1;
    int hg = blockIdx.x & 1;
    int t = threadIdx.x;
    int d4 = t * 4;
    float4 acc[HH];
    #pragma unroll
    for (int h = 0; h < HH; h++) { acc[h].x=0.f; acc[h].y=0.f; acc[h].z=0.f; acc[h].w=0.f; }

    for (int c = cg; c < NCELL; c += K4_CG) {
        float4 a = *reinterpret_cast<const float4*>(g_A + c*DD + d4);
        if (a.x == 0.f && a.y == 0.f && a.z == 0.f && a.w == 0.f) continue;
        const float* base = E + c*(CHH*DD) + hg*HH*DD + d4;
        #pragma unroll
        for (int h = 0; h < HH; h++) {
            float4 e = *reinterpret_cast<const float4*>(base + h*DD);
            acc[h].x += a.x * e.x;
            acc[h].y += a.y * e.y;
            acc[h].z += a.z * e.z;
            acc[h].w += a.w * e.w;
        }
    }
    float* pb = g_part + blockIdx.x * (HH*DD);
    #pragma unroll
    for (int h = 0; h < HH; h++)
        *reinterpret_cast<float4*>(pb + h*DD + d4) = acc[h];
}

/* ---------------- K5: reduce partials -> d_out ---------------------------- */
__global__ void k_reduce(float* __restrict__ out) {
    int idx = blockIdx.x * blockDim.x + threadIdx.x;   /* 5760 threads */
    if (idx >= (NHH * DD) / 4) return;
    int h  = idx / (DD/4);
    int d4 = (idx - h*(DD/4)) * 4;
    int g  = h / HH;
    int hh = h - g*HH;
    float ax=0.f, ay=0.f, az=0.f, aw=0.f;
    #pragma unroll 4
    for (int cg = 0; cg < K4_CG; cg++) {
        const float4 v = *reinterpret_cast<const float4*>(
            g_part + (cg*2 + g) * (HH*DD) + hh*DD + d4);
        ax += v.x; ay += v.y; az += v.z; aw += v.w;
    }
    float4 o; o.x=ax; o.y=ay; o.z=az; o.w=aw;
    *reinterpret_cast<float4*>(out + h*DD + d4) = o;
}

/* ---------------- launcher ------------------------------------------------ */
extern "C" void kernel_launch(void* const* d_in, const int* in_sizes, int n_in,
                              void* d_out, int out_size) {
    const float* samples = (const float*)d_in[0];
    const float* lastp   = (const float*)d_in[1];
    const float* E       = (const float*)d_in[2];
    /* robust identification by size */
    for (int i = 0; i < n_in; i++) {
        if (in_sizes[i] == NS * 3)            samples = (const float*)d_in[i];
        else if (in_sizes[i] == 3)            lastp   = (const float*)d_in[i];
        else if (in_sizes[i] > 1000000)       E       = (const float*)d_in[i];
    }

    k_zero    <<<(NCELL + 255)/256, 256>>>();
    k_prep    <<<(NS + 255)/256, 256>>>(samples, lastp);
    k_scan    <<<1, 1024>>>();
    k_scatter <<<(NS + 255)/256, 256>>>();
    k_sortbins<<<(NCELL + 255)/256, 256>>>();
    k_density <<<NS, 192>>>(E);
    k_chunksum<<<(NCHUNK*DD)/256, 256>>>();
    k_wgt     <<<(NCHUNK*DD)/256, 256>>>();
    k_A       <<<NCELL, 192>>>();
    k_out     <<<K4_GRID, 192>>>(E);
    k_reduce  <<<30, 192>>>((float*)d_out);
    (void)out_size;
}

// round 2
// speedup vs baseline: 1.2730x; 1.2730x over previous
#include <cuda_runtime.h>
#include <cuda_fp16.h>
#include <math.h>

#define GD     17
#define NS     4096
#define DD     768
#define NHH    30
#define CHH    31
#define NCELL  4913      /* 17^3 */
#define NCHUNK 64
#define CHUNK  64
#define K4_CG  296
#define K4_GRID (K4_CG*2)
#define HH     15        /* h per group */
#define MAXCAND 1536

/* ---------------- scratch (static device globals: allocation-free) ------- */
__device__ __align__(16) float  g_w[NS][12];
__device__              int    g_cells[NS][3];
__device__              float  g_dist[NS];
__device__              int    g_bin[NS];
__device__              int    g_binCount[NCELL];
__device__              int    g_binStart[NCELL + 1];
__device__              int    g_binCursor[NCELL];
__device__              int    g_binSamples[NS];
__device__ __align__(16) __half g_Ed[NCELL * DD];      /* fp16 density slice */
__device__ __align__(16) float  g_sd[NS * DD];          /* fp32: scan precision */
__device__ __align__(16) __half g_wgt[NS * DD];         /* fp16 weights */
__device__ __align__(16) float  g_S[NCHUNK * DD];
__device__ __align__(16) float  g_A[NCELL * DD];
__device__ __align__(16) float  g_part[K4_GRID * HH * DD];

/* ---------------- K-init: clear bin counts + fp16-convert density -------- */
__global__ void k_init(const float* __restrict__ E) {
    int i = blockIdx.x * blockDim.x + threadIdx.x;
    if (i < NCELL) g_binCount[i] = 0;
    if (i < NCELL * DD) {
        int cell = i / DD;
        int d    = i - cell * DD;
        g_Ed[i] = __float2half(E[cell * (CHH*DD) + NHH*DD + d]);
    }
}

/* ---------------- K0: per-sample prep (weights, cells, dist, bin) -------- */
__global__ void k_prep(const float* __restrict__ samples,
                       const float* __restrict__ lastp) {
    int n = blockIdx.x * blockDim.x + threadIdx.x;
    if (n >= NS) return;

    float s[3] = { samples[3*n], samples[3*n+1], samples[3*n+2] };
    float nx[3];
    if (n < NS - 1) { nx[0]=samples[3*n+3]; nx[1]=samples[3*n+4]; nx[2]=samples[3*n+5]; }
    else            { nx[0]=lastp[0];       nx[1]=lastp[1];       nx[2]=lastp[2]; }
    float e0=s[0]-nx[0], e1=s[1]-nx[1], e2=s[2]-nx[2];
    g_dist[n] = sqrtf(e0*e0 + e1*e1 + e2*e2);

    int fi[3];
    #pragma unroll
    for (int a = 0; a < 3; a++) {
        float p  = s[a] + 8.0f;
        float f  = floorf(p);
        int  fii = (int)f;
        float dd = p - f;
        int  q   = (a == 0) ? (fii + 1) : (int)ceilf(p);   /* x uses f+1; y,z use ceil */
        int c0 = fii;
        int c1 = min(q, GD - 1);
        int c2 = max(fii - 1, 0);
        int c3 = min(q + 1, GD - 1);
        float mlo = (fii > 0)      ? 1.0f : 0.0f;
        float mhi = (fii + 2 < GD) ? 1.0f : 0.0f;
        float inv = 1.0f / (2.0f + mlo + mhi);
        g_w[n][a*4+0] = (2.0f - dd) * inv;
        g_w[n][a*4+1] = (1.0f + dd) * inv;
        g_w[n][a*4+2] = (1.0f - dd) * mlo * inv;
        g_w[n][a*4+3] = dd * mhi * inv;
        g_cells[n][a] = c0 | (c1 << 8) | (c2 << 16) | (c3 << 24);
        fi[a] = fii;
    }
    int bin = (fi[0]*GD + fi[1])*GD + fi[2];
    g_bin[n] = bin;
    atomicAdd(&g_binCount[bin], 1);
}

/* ---------------- K-build: scan + scatter + per-bin sort (one block) ----- */
__global__ void k_build() {
    __shared__ int sm[1024];
    __shared__ int carry;
    int t = threadIdx.x;
    if (t == 0) carry = 0;
    __syncthreads();
    /* phase 1: exclusive prefix scan of bin counts */
    for (int base = 0; base < NCELL; base += 1024) {
        int idx = base + t;
        int v = (idx < NCELL) ? g_binCount[idx] : 0;
        sm[t] = v;
        __syncthreads();
        for (int off = 1; off < 1024; off <<= 1) {
            int x = (t >= off) ? sm[t - off] : 0;
            __syncthreads();
            sm[t] += x;
            __syncthreads();
        }
        if (idx < NCELL) {
            int excl = carry + sm[t] - v;
            g_binStart[idx]  = excl;
            g_binCursor[idx] = excl;
        }
        __syncthreads();
        if (t == 0) carry += sm[1023];
        __syncthreads();
    }
    if (t == 0) g_binStart[NCELL] = carry;
    __syncthreads();
    /* phase 2: scatter sample ids */
    for (int n = t; n < NS; n += 1024) {
        int pos = atomicAdd(&g_binCursor[g_bin[n]], 1);
        g_binSamples[pos] = n;
    }
    __syncthreads();
    /* phase 3: insertion-sort each bin for determinism */
    for (int b = t; b < NCELL; b += 1024) {
        int s0 = g_binStart[b], s1 = g_binStart[b + 1];
        for (int i = s0 + 1; i < s1; i++) {
            int v = g_binSamples[i];
            int j = i - 1;
            while (j >= s0 && g_binSamples[j] > v) { g_binSamples[j+1] = g_binSamples[j]; j--; }
            g_binSamples[j + 1] = v;
        }
    }
}

/* ---------------- K1: density channel interp (fp16 table) -> sd ---------- */
__global__ void __launch_bounds__(192) k_density() {
    __shared__ float scoef[64];
    __shared__ int   soff[64];
    __shared__ float sw[12];
    __shared__ int   sc[3];
    int n = blockIdx.x;
    int t = threadIdx.x;
    if (t < 12) sw[t] = g_w[n][t];
    if (t < 3)  sc[t] = g_cells[n][t];
    __syncthreads();
    if (t < 64) {
        int i = t >> 4, j = (t >> 2) & 3, k = t & 3;
        int cx = (sc[0] >> (8*i)) & 255;
        int cy = (sc[1] >> (8*j)) & 255;
        int cz = (sc[2] >> (8*k)) & 255;
        scoef[t] = sw[i] * sw[4 + j] * sw[8 + k];
        soff[t]  = ((cx*GD + cy)*GD + cz) * DD;
    }
    __syncthreads();
    int d4 = t * 4;
    float ax = 0.f, ay = 0.f, az = 0.f, aw = 0.f;
    #pragma unroll 4
    for (int m = 0; m < 64; m++) {
        float c = scoef[m];
        if (c != 0.0f) {
            uint2 u = *reinterpret_cast<const uint2*>(g_Ed + soff[m] + d4);
            float2 f0 = __half22float2(*reinterpret_cast<const __half2*>(&u.x));
            float2 f1 = __half22float2(*reinterpret_cast<const __half2*>(&u.y));
            ax += c * f0.x; ay += c * f0.y; az += c * f1.x; aw += c * f1.y;
        }
    }
    float dist = g_dist[n];
    float4 o;
    o.x = fmaxf(ax, 0.f) * dist;
    o.y = fmaxf(ay, 0.f) * dist;
    o.z = fmaxf(az, 0.f) * dist;
    o.w = fmaxf(aw, 0.f) * dist;
    *reinterpret_cast<float4*>(g_sd + n*DD + d4) = o;
}

/* ---------------- K2a: chunk partial sums of sd --------------------------- */
__global__ void k_chunksum() {
    int idx = blockIdx.x * blockDim.x + threadIdx.x;   /* NCHUNK*DD threads */
    int chunk = idx / DD;
    int d = idx - chunk * DD;
    int base = chunk * CHUNK * DD + d;
    float s = 0.f;
    #pragma unroll 8
    for (int i = 0; i < CHUNK; i++) s += g_sd[base + i*DD];
    g_S[chunk*DD + d] = s;
}

/* ---------------- K2b: exclusive scan + weights (fp16 out) ---------------- */
__global__ void k_wgt() {
    int idx = blockIdx.x * blockDim.x + threadIdx.x;
    int chunk = idx / DD;
    int d = idx - chunk * DD;
    float excl = 0.f;
    for (int j = 0; j < chunk; j++) excl += g_S[j*DD + d];
    int base = chunk * CHUNK * DD + d;
    for (int i = 0; i < CHUNK; i++) {
        float sd = g_sd[base + i*DD];
        float T = __expf(-excl);
        float alpha = 1.0f - __expf(-sd);
        g_wgt[base + i*DD] = __float2half(T * alpha);
        excl += sd;
    }
}

/* ---------------- K3: A[c,d] gather (cell-centric, fp16 wgt) -------------- */
__global__ void __launch_bounds__(192) k_A() {
    __shared__ int   slist[MAXCAND];
    __shared__ float scoef[MAXCAND];
    __shared__ int   scnt[64];
    __shared__ int   soff2[64];
    __shared__ int   sstart[64];
    __shared__ int   s_tot;
    int c = blockIdx.x;
    int iz = c % GD; int r = c / GD; int iy = r % GD; int ix = r / GD;
    int x0 = max(ix-2,0), x1 = min(ix+1,GD-1);
    int y0 = max(iy-2,0), y1 = min(iy+1,GD-1);
    int z0 = max(iz-2,0), z1 = min(iz+1,GD-1);
    int nxb = x1-x0+1, nyb = y1-y0+1, nzb = z1-z0+1;
    int nb = nxb * nyb * nzb;
    int t = threadIdx.x;

    if (t < nb) {
        int bi = t / (nyb*nzb); int rr = t - bi*(nyb*nzb);
        int bj = rr / nzb;      int bk = rr - bj*nzb;
        int b = ((x0+bi)*GD + (y0+bj))*GD + (z0+bk);
        sstart[t] = g_binStart[b];
        scnt[t]   = g_binStart[b+1] - g_binStart[b];
    }
    __syncthreads();
    if (t == 0) {
        int acc = 0;
        for (int i = 0; i < nb; i++) { soff2[i] = acc; acc += scnt[i]; }
        s_tot = (acc < MAXCAND) ? acc : MAXCAND;
    }
    __syncthreads();
    int tot = s_tot;
    if (t < nb) {
        int off = soff2[t], st = sstart[t], cn = scnt[t];
        for (int k = 0; k < cn; k++)
            if (off + k < MAXCAND) slist[off + k] = g_binSamples[st + k];
    }
    __syncthreads();
    /* coefficients: one candidate per thread */
    for (int i = t; i < tot; i += 192) {
        int n = slist[i];
        int cpx = g_cells[n][0], cpy = g_cells[n][1], cpz = g_cells[n][2];
        float wx = 0.f, wy = 0.f, wz = 0.f;
        #pragma unroll
        for (int u = 0; u < 4; u++) {
            if (((cpx >> (8*u)) & 255) == ix) wx += g_w[n][u];
            if (((cpy >> (8*u)) & 255) == iy) wy += g_w[n][4 + u];
            if (((cpz >> (8*u)) & 255) == iz) wz += g_w[n][8 + u];
        }
        scoef[i] = wx * wy * wz;
        slist[i] = n * DD;
    }
    __syncthreads();
    int d4 = t * 4;
    float ax = 0.f, ay = 0.f, az = 0.f, aw = 0.f;
    for (int i = 0; i < tot; i++) {
        float cf = scoef[i];
        if (cf != 0.0f) {
            uint2 u = *reinterpret_cast<const uint2*>(g_wgt + slist[i] + d4);
            float2 f0 = __half22float2(*reinterpret_cast<const __half2*>(&u.x));
            float2 f1 = __half22float2(*reinterpret_cast<const __half2*>(&u.y));
            ax += cf * f0.x; ay += cf * f0.y; az += cf * f1.x; aw += cf * f1.y;
        }
    }
    float4 o; o.x = ax; o.y = ay; o.z = az; o.w = aw;
    *reinterpret_cast<float4*>(g_A + c*DD + d4) = o;
}

/* ---------------- K4: out partials = sum_c A[c,d]*E[c,h,d] ---------------- */
__global__ void __launch_bounds__(192, 2) k_out(const float* __restrict__ E) {
    int cg = blockIdx.x >> 1;
    int hg = blockIdx.x & 1;
    int t = threadIdx.x;
    int d4 = t * 4;
    float4 acc[HH];
    #pragma unroll
    for (int h = 0; h < HH; h++) { acc[h].x=0.f; acc[h].y=0.f; acc[h].z=0.f; acc[h].w=0.f; }

    for (int c = cg; c < NCELL; c += K4_CG) {
        float4 a = *reinterpret_cast<const float4*>(g_A + c*DD + d4);
        if (a.x == 0.f && a.y == 0.f && a.z == 0.f && a.w == 0.f) continue;
        const float4* base = reinterpret_cast<const float4*>(E + c*(CHH*DD) + hg*HH*DD + d4);
        #pragma unroll
        for (int h = 0; h < HH; h++) {
            float4 e = __ldcs(base + h*(DD/4));
            acc[h].x += a.x * e.x;
            acc[h].y += a.y * e.y;
            acc[h].z += a.z * e.z;
            acc[h].w += a.w * e.w;
        }
    }
    float* pb = g_part + blockIdx.x * (HH*DD);
    #pragma unroll
    for (int h = 0; h < HH; h++)
        *reinterpret_cast<float4*>(pb + h*DD + d4) = acc[h];
}

/* ---------------- K5: reduce partials -> d_out ---------------------------- */
__global__ void k_reduce(float* __restrict__ out) {
    int idx = blockIdx.x * blockDim.x + threadIdx.x;   /* 5760 threads */
    if (idx >= (NHH * DD) / 4) return;
    int h  = idx / (DD/4);
    int d4 = (idx - h*(DD/4)) * 4;
    int g  = h / HH;
    int hh = h - g*HH;
    float ax=0.f, ay=0.f, az=0.f, aw=0.f;
    #pragma unroll 4
    for (int cg = 0; cg < K4_CG; cg++) {
        const float4 v = *reinterpret_cast<const float4*>(
            g_part + (cg*2 + g) * (HH*DD) + hh*DD + d4);
        ax += v.x; ay += v.y; az += v.z; aw += v.w;
    }
    float4 o; o.x=ax; o.y=ay; o.z=az; o.w=aw;
    *reinterpret_cast<float4*>(out + h*DD + d4) = o;
}

/* ---------------- launcher ------------------------------------------------ */
extern "C" void kernel_launch(void* const* d_in, const int* in_sizes, int n_in,
                              void* d_out, int out_size) {
    const float* samples = (const float*)d_in[0];
    const float* lastp   = (const float*)d_in[1];
    const float* E       = (const float*)d_in[2];
    for (int i = 0; i < n_in; i++) {
        if (in_sizes[i] == NS * 3)            samples = (const float*)d_in[i];
        else if (in_sizes[i] == 3)            lastp   = (const float*)d_in[i];
        else if (in_sizes[i] > 1000000)       E       = (const float*)d_in[i];
    }

    k_init    <<<(NCELL*DD + 255)/256, 256>>>(E);
    k_prep    <<<(NS + 255)/256, 256>>>(samples, lastp);
    k_build   <<<1, 1024>>>();
    k_density <<<NS, 192>>>();
    k_chunksum<<<(NCHUNK*DD)/256, 256>>>();
    k_wgt     <<<(NCHUNK*DD)/256, 256>>>();
    k_A       <<<NCELL, 192>>>();
    k_out     <<<K4_GRID, 192>>>(E);
    k_reduce  <<<30, 192>>>((float*)d_out);
    (void)out_size;
}